// round 2
// baseline (speedup 1.0000x reference)
#include <cuda_runtime.h>
#include <cuda_bf16.h>

#define Bb 256
#define Tt 1024
#define INF 128
#define Hh 10
#define OUTD 128
#define BT (Bb*Tt)

// Scratch (no cudaMalloc allowed): device globals
__device__ float g_xp0[(size_t)BT * Hh];   // [BT][10]
__device__ float g_out2[(size_t)BT * Hh];  // [BT][10]

// ---------------------------------------------------------------------------
// Kernel 1: xp0[row][h] = dot(x[row,:], W_ih0[h,:]) + b_ih0[h] + b_hh0[h]
// 1 row per thread (grid 1024x256 for occupancy); x read as float4;
// W_ih0 staged transposed in smem as float4 Wq[f][3] (broadcast LDS).
// ---------------------------------------------------------------------------
__global__ __launch_bounds__(256) void k1_inproj(
    const float* __restrict__ x,
    const float* __restrict__ W_ih0,
    const float* __restrict__ b_ih0,
    const float* __restrict__ b_hh0)
{
    __shared__ float4 Wq[128][3];   // Wq[f][g] holds W_ih0[4g..4g+3][f] (h>=10 -> 0)
    __shared__ float bs[16];
    int tid = threadIdx.x;
    for (int i = tid; i < 128 * 3; i += blockDim.x) {
        int f = i / 3, g = i % 3;
        float4 v;
        v.x = (4*g+0 < Hh) ? W_ih0[(4*g+0)*128 + f] : 0.f;
        v.y = (4*g+1 < Hh) ? W_ih0[(4*g+1)*128 + f] : 0.f;
        v.z = (4*g+2 < Hh) ? W_ih0[(4*g+2)*128 + f] : 0.f;
        v.w = (4*g+3 < Hh) ? W_ih0[(4*g+3)*128 + f] : 0.f;
        Wq[f][g] = v;
    }
    if (tid < Hh) bs[tid] = b_ih0[tid] + b_hh0[tid];
    __syncthreads();

    size_t row = (size_t)blockIdx.x * blockDim.x + tid;
    const float4* x4 = (const float4*)x;

    float acc[Hh];
    #pragma unroll
    for (int h = 0; h < Hh; h++) acc[h] = bs[h];

    #pragma unroll 8
    for (int c = 0; c < 32; c++) {
        float4 xv = x4[row * 32 + c];
        #pragma unroll
        for (int q = 0; q < 4; q++) {
            int f = 4 * c + q;
            float4 wa = Wq[f][0], wb = Wq[f][1], wc = Wq[f][2];
            float xs = (q == 0) ? xv.x : (q == 1) ? xv.y : (q == 2) ? xv.z : xv.w;
            acc[0] = fmaf(xs, wa.x, acc[0]);
            acc[1] = fmaf(xs, wa.y, acc[1]);
            acc[2] = fmaf(xs, wa.z, acc[2]);
            acc[3] = fmaf(xs, wa.w, acc[3]);
            acc[4] = fmaf(xs, wb.x, acc[4]);
            acc[5] = fmaf(xs, wb.y, acc[5]);
            acc[6] = fmaf(xs, wb.z, acc[6]);
            acc[7] = fmaf(xs, wb.w, acc[7]);
            acc[8] = fmaf(xs, wc.x, acc[8]);
            acc[9] = fmaf(xs, wc.y, acc[9]);
        }
    }
    float* o = g_xp0 + row * Hh;
    #pragma unroll
    for (int h = 0; h < Hh; h++) o[h] = acc[h];
}

// ---------------------------------------------------------------------------
// Kernel 2: fused 2-layer ReLU RNN scan. One warp per batch.
// Replicated-h design: every lane holds full v0[10], v1[10] in registers.
// Lane j (clamped) computes its own h0n/h1n element; 20 shfls/step total
// (10 to rebroadcast h0n, 10 for h1n). W_hh1*v1 dot hoisted off the
// h0n-dependent critical path. Store is a single predicated STG.
// ---------------------------------------------------------------------------
__global__ __launch_bounds__(64) void k2_scan(
    const float* __restrict__ W_hh0,
    const float* __restrict__ W_ih1,
    const float* __restrict__ W_hh1,
    const float* __restrict__ b_ih1,
    const float* __restrict__ b_hh1,
    float* __restrict__ dout)
{
    const unsigned FULL = 0xffffffffu;
    int warp = (blockIdx.x * blockDim.x + threadIdx.x) >> 5;   // = batch b
    int lane = threadIdx.x & 31;
    int j = lane < Hh ? lane : Hh - 1;

    float w0r[Hh], wi1r[Hh], w1r[Hh];
    #pragma unroll
    for (int k = 0; k < Hh; k++) {
        w0r[k]  = W_hh0[j * Hh + k];
        wi1r[k] = W_ih1[j * Hh + k];
        w1r[k]  = W_hh1[j * Hh + k];
    }
    float bias1 = b_ih1[j] + b_hh1[j];

    const float* xp = g_xp0 + (size_t)warp * Tt * Hh;
    float* o2 = g_out2 + (size_t)warp * Tt * Hh;

    float v0[Hh], v1[Hh];
    #pragma unroll
    for (int k = 0; k < Hh; k++) { v0[k] = 0.f; v1[k] = 0.f; }
    float last0 = 0.f, last1 = 0.f;

    float xa[8], xb[8];
    #pragma unroll
    for (int d = 0; d < 8; d++) xa[d] = xp[d * Hh + j];

    for (int tb = 0; tb < Tt; tb += 8) {
        if (tb + 8 < Tt) {
            #pragma unroll
            for (int d = 0; d < 8; d++) xb[d] = xp[(tb + 8 + d) * Hh + j];
        }
        #pragma unroll
        for (int d = 0; d < 8; d++) {
            // layer-1 recurrent dot (independent of h0n -> off critical path)
            float r0 = bias1, r1 = 0.f;
            #pragma unroll
            for (int k = 0; k < Hh; k += 2) {
                r0 = fmaf(w1r[k],     v1[k],     r0);
                r1 = fmaf(w1r[k + 1], v1[k + 1], r1);
            }
            // layer-0 update (4 accumulators, depth ~3)
            float a0 = xa[d], a1 = 0.f, a2 = 0.f, a3 = 0.f;
            a0 = fmaf(w0r[0], v0[0], a0);
            a1 = fmaf(w0r[1], v0[1], a1);
            a2 = fmaf(w0r[2], v0[2], a2);
            a3 = fmaf(w0r[3], v0[3], a3);
            a0 = fmaf(w0r[4], v0[4], a0);
            a1 = fmaf(w0r[5], v0[5], a1);
            a2 = fmaf(w0r[6], v0[6], a2);
            a3 = fmaf(w0r[7], v0[7], a3);
            a0 = fmaf(w0r[8], v0[8], a0);
            a1 = fmaf(w0r[9], v0[9], a1);
            float h0n = fmaxf((a0 + a1) + (a2 + a3), 0.f);

            // rebroadcast h0n (10 shfls, independent)
            #pragma unroll
            for (int k = 0; k < Hh; k++) v0[k] = __shfl_sync(FULL, h0n, k);

            // layer-1 input dot
            float c0 = r0, c1 = r1, c2 = 0.f, c3 = 0.f;
            c0 = fmaf(wi1r[0], v0[0], c0);
            c1 = fmaf(wi1r[1], v0[1], c1);
            c2 = fmaf(wi1r[2], v0[2], c2);
            c3 = fmaf(wi1r[3], v0[3], c3);
            c0 = fmaf(wi1r[4], v0[4], c0);
            c1 = fmaf(wi1r[5], v0[5], c1);
            c2 = fmaf(wi1r[6], v0[6], c2);
            c3 = fmaf(wi1r[7], v0[7], c3);
            c0 = fmaf(wi1r[8], v0[8], c0);
            c1 = fmaf(wi1r[9], v0[9], c1);
            float h1n = fmaxf((c0 + c1) + (c2 + c3), 0.f);

            float* addr = o2 + (size_t)(tb + d) * Hh + lane;
            if (lane < Hh) *addr = h1n;   // predicated STG (single statement)

            // rebroadcast h1n
            #pragma unroll
            for (int k = 0; k < Hh; k++) v1[k] = __shfl_sync(FULL, h1n, k);

            last0 = h0n; last1 = h1n;
        }
        #pragma unroll
        for (int d = 0; d < 8; d++) xa[d] = xb[d];
    }

    float* hid = dout + (size_t)BT * OUTD;       // hidden: [2][B][H]
    float* a0p = hid + warp * Hh + lane;
    float* a1p = hid + Bb * Hh + warp * Hh + lane;
    if (lane < Hh) *a0p = last0;                 // layer 0 final state
    if (lane < Hh) *a1p = last1;                 // layer 1 final state
}

// ---------------------------------------------------------------------------
// Kernel 3: logits = out2 @ W_lin^T + b_lin, softmax over 128.
// One warp per row; lane handles outputs 4l..4l+3; coalesced STG.128.
// ---------------------------------------------------------------------------
__global__ __launch_bounds__(256) void k3_head(
    const float* __restrict__ W_lin,
    const float* __restrict__ b_lin,
    float* __restrict__ out)
{
    const unsigned FULL = 0xffffffffu;
    __shared__ float Wl[OUTD * Hh];
    __shared__ float bl[OUTD];
    int tid = threadIdx.x;
    for (int i = tid; i < OUTD * Hh; i += blockDim.x) Wl[i] = W_lin[i];
    for (int i = tid; i < OUTD; i += blockDim.x) bl[i] = b_lin[i];
    __syncthreads();

    int lane = tid & 31;
    int wib  = tid >> 5;
    float wl[4][Hh], bb[4];
    #pragma unroll
    for (int c = 0; c < 4; c++) {
        int o = 4 * lane + c;
        bb[c] = bl[o];
        #pragma unroll
        for (int k = 0; k < Hh; k++) wl[c][k] = Wl[o * Hh + k];
    }

    int wpb = blockDim.x >> 5;
    int gw  = blockIdx.x * wpb + wib;
    int nw  = gridDim.x * wpb;
    for (int row = gw; row < BT; row += nw) {
        float v = g_out2[(size_t)row * Hh + (lane < Hh ? lane : 0)];
        float hk[Hh];
        #pragma unroll
        for (int k = 0; k < Hh; k++) hk[k] = __shfl_sync(FULL, v, k);

        float acc[4];
        #pragma unroll
        for (int c = 0; c < 4; c++) {
            acc[c] = bb[c];
            #pragma unroll
            for (int k = 0; k < Hh; k++) acc[c] = fmaf(hk[k], wl[c][k], acc[c]);
        }
        float m = fmaxf(fmaxf(acc[0], acc[1]), fmaxf(acc[2], acc[3]));
        #pragma unroll
        for (int s = 16; s > 0; s >>= 1)
            m = fmaxf(m, __shfl_xor_sync(FULL, m, s));
        float e0 = __expf(acc[0] - m), e1 = __expf(acc[1] - m);
        float e2 = __expf(acc[2] - m), e3 = __expf(acc[3] - m);
        float s = e0 + e1 + e2 + e3;
        #pragma unroll
        for (int sh = 16; sh > 0; sh >>= 1)
            s += __shfl_xor_sync(FULL, s, sh);
        float r = __frcp_rn(s);
        float4 res = make_float4(e0 * r, e1 * r, e2 * r, e3 * r);
        ((float4*)(out + (size_t)row * OUTD))[lane] = res;
    }
}

// ---------------------------------------------------------------------------
extern "C" void kernel_launch(void* const* d_in, const int* in_sizes, int n_in,
                              void* d_out, int out_size)
{
    const float* x      = (const float*)d_in[0];
    const float* W_ih0  = (const float*)d_in[1];
    const float* W_hh0  = (const float*)d_in[2];
    const float* b_ih0  = (const float*)d_in[3];
    const float* b_hh0  = (const float*)d_in[4];
    const float* W_ih1  = (const float*)d_in[5];
    const float* W_hh1  = (const float*)d_in[6];
    const float* b_ih1  = (const float*)d_in[7];
    const float* b_hh1  = (const float*)d_in[8];
    const float* W_lin  = (const float*)d_in[9];
    const float* b_lin  = (const float*)d_in[10];
    float* out = (float*)d_out;

    k1_inproj<<<1024, 256>>>(x, W_ih0, b_ih0, b_hh0);             // 1 row/thread
    k2_scan<<<128, 64>>>(W_hh0, W_ih1, W_hh1, b_ih1, b_hh1, out); // 256 warps = B
    k3_head<<<2048, 256>>>(W_lin, b_lin, out);                    // grid-stride rows
}